// round 14
// baseline (speedup 1.0000x reference)
#include <cuda_runtime.h>
#include <cuda_bf16.h>
#include <cuda_fp16.h>
#include <cstdint>

#define MAXN 50000
#define MAXE 800000
#define LLAYERS 3

// ================= helpers =================
__device__ __forceinline__ uint32_t packh(float lo_v, float hi_v) {
    uint32_t r;
    asm("cvt.rn.f16x2.f32 %0, %1, %2;" : "=r"(r) : "f"(hi_v), "f"(lo_v));
    return r;
}

__device__ __forceinline__ void mma_f16(float* c, const uint32_t* a, uint32_t b0, uint32_t b1) {
    asm volatile(
        "mma.sync.aligned.m16n8k16.row.col.f32.f16.f16.f32 "
        "{%0,%1,%2,%3}, {%4,%5,%6,%7}, {%8,%9}, {%0,%1,%2,%3};\n"
        : "+f"(c[0]), "+f"(c[1]), "+f"(c[2]), "+f"(c[3])
        : "r"(a[0]), "r"(a[1]), "r"(a[2]), "r"(a[3]), "r"(b0), "r"(b1));
}

// ================= scratch (static device globals) =================
__device__ float g_h1n[MAXN * 256];
__device__ float g_ab [MAXN * 256];
__device__ float g_x  [MAXN * 128];
__device__ float g_agg[MAXN * 128];
__device__ float g_Wab [LLAYERS * 256 * 256];
__device__ float g_Wc  [LLAYERS * 128 * 128];
__device__ float g_bch [LLAYERS * 256];
// sorted-edge machinery
__device__ int g_hist[MAXN];
__device__ int g_cursor[MAXN];
__device__ int g_rowptr[MAXN + 1];
__device__ int g_bsum[256];
__device__ int g_perm[MAXE];
// per-layer packed fp16 transposed edge weights, 88064 elems / layer
#define WP_LAYER_ELEMS 88064
__device__ uint4 g_wpack[LLAYERS * WP_LAYER_ELEMS * 2 / 16];
// per-layer node weights: [W1hi 256x136][W1lo][WABhi 256x264][WABlo]
#define NP_LAYER_ELEMS 204800
#define NP_W1  0
#define NP_WAB 69632
__device__ uint4 g_wnode[LLAYERS * NP_LAYER_ELEMS * 2 / 16];
__device__ uint4 g_wf[2 * 64 * 136 * 2 / 16];

#define WO_WE1H 0
#define WO_WE1L 9216
#define WO_WCH  18432
#define WO_WCL  35840
#define WO_WM2H 53248
#define WO_WM2L 70656

// ================= fused weight-fuse kernel =================
__global__ __launch_bounds__(256) void fuse_all(
    const float* __restrict__ Wn2, const float* __restrict__ Wm1,
    const float* __restrict__ We2, const float* __restrict__ bn2,
    const float* __restrict__ be2, const float* __restrict__ bm1,
    float* __restrict__ Wab, float* __restrict__ Wc, float* __restrict__ bch)
{
    int b = blockIdx.x, tid = threadIdx.x;
    if (b < 768) {
        int l = b >> 8;
        int idx = (b & 255) * 256 + tid;
        const float* wn2 = Wn2 + (size_t)l * 256 * 128;
        const float* wm1 = Wm1 + (size_t)l * 320 * 128;
        int k = idx >> 8, j = idx & 255;
        const float* wm = (j < 128) ? (wm1 + j) : (wm1 + 128 * 128 + (j - 128));
        float acc = 0.f;
        #pragma unroll 4
        for (int t = 0; t < 128; t++) acc += wn2[k * 128 + t] * wm[t * 128];
        Wab[(size_t)l * 65536 + idx] = acc;
    } else if (b < 960) {
        int lb = b - 768;
        int l = lb / 64;
        int idx = (lb % 64) * 256 + tid;
        const float* we2 = We2 + (size_t)l * 128 * 64;
        const float* wm1 = Wm1 + (size_t)l * 320 * 128;
        int k = idx >> 7, j = idx & 127;
        float acc = 0.f;
        #pragma unroll 4
        for (int t = 0; t < 64; t++) acc += we2[k * 64 + t] * wm1[(256 + t) * 128 + j];
        Wc[(size_t)l * 16384 + idx] = acc;
    } else {
        int lb = b - 960;
        int l = lb / 16;
        int lane = tid & 31;
        int j = (lb % 16) * 8 + (tid >> 5);
        const float* wm1 = Wm1 + (size_t)l * 320 * 128;
        const float* bn2l = bn2 + l * 128;
        const float* be2l = be2 + l * 64;
        float acc = 0.f;
        #pragma unroll
        for (int k = lane; k < 128; k += 32)
            acc += bn2l[k] * (wm1[k * 128 + j] + wm1[(128 + k) * 128 + j]);
        #pragma unroll
        for (int t = lane; t < 64; t += 32)
            acc += be2l[t] * wm1[(256 + t) * 128 + j];
        #pragma unroll
        for (int o = 16; o; o >>= 1) acc += __shfl_xor_sync(0xffffffffu, acc, o);
        if (lane == 0) {
            float half = 0.5f * (bm1[l * 128 + j] + acc);
            bch[l * 256 + j] = half;
            bch[l * 256 + 128 + j] = half;
        }
    }
}

// ================= fused fp16 hi/lo transpose prep kernel =================
__device__ __forceinline__ void splitw(float w, __half* hi, __half* lo, int o) {
    __half h = __float2half_rn(w);
    hi[o] = h;
    lo[o] = __float2half_rn(w - __half2float(h));
}

__global__ __launch_bounds__(256) void prep_all(
    const float* __restrict__ We1, const float* __restrict__ WcG,
    const float* __restrict__ Wm2, const float* __restrict__ Wn1,
    const float* __restrict__ WabG, const float* __restrict__ Wf,
    __half* __restrict__ wb, __half* __restrict__ nbw,
    __half* __restrict__ wfb)
{
    int b = blockIdx.x, tid = threadIdx.x;
    if (b < 96) {
        int l = b / 32;
        int idx = (b % 32) * 256 + tid;
        int n = idx >> 6, k = idx & 63;
        float w = We1[(size_t)l * 8192 + k * 128 + n];
        __half* base = wb + (size_t)l * WP_LAYER_ELEMS;
        splitw(w, base + WO_WE1H, base + WO_WE1L, n * 72 + k);
    } else if (b < 288) {
        int lb = b - 96;
        int l = lb / 64;
        int idx = (lb % 64) * 256 + tid;
        int n = idx >> 7, k = idx & 127;
        float w = WcG[(size_t)l * 16384 + k * 128 + n];
        __half* base = wb + (size_t)l * WP_LAYER_ELEMS;
        splitw(w, base + WO_WCH, base + WO_WCL, n * 136 + k);
    } else if (b < 480) {
        int lb = b - 288;
        int l = lb / 64;
        int idx = (lb % 64) * 256 + tid;
        int n = idx >> 7, k = idx & 127;
        float w = Wm2[(size_t)l * 16384 + k * 128 + n];
        __half* base = wb + (size_t)l * WP_LAYER_ELEMS;
        splitw(w, base + WO_WM2H, base + WO_WM2L, n * 136 + k);
    } else if (b < 864) {
        int lb = b - 480;
        int l = lb / 128;
        int idx = (lb % 128) * 256 + tid;
        int n = idx & 255, k = idx >> 8;
        float w = Wn1[(size_t)l * 32768 + idx];
        __half* base = nbw + (size_t)l * NP_LAYER_ELEMS + NP_W1;
        splitw(w, base, base + 256 * 136, n * 136 + k);
    } else if (b < 1632) {
        int lb = b - 864;
        int l = lb / 256;
        int idx = (lb % 256) * 256 + tid;
        int n = idx & 255, k = idx >> 8;
        float w = WabG[(size_t)l * 65536 + idx];
        __half* base = nbw + (size_t)l * NP_LAYER_ELEMS + NP_WAB;
        splitw(w, base, base + 256 * 264, n * 264 + k);
    } else {
        int idx = (b - 1632) * 256 + tid;
        int n = idx & 63, k = idx >> 6;
        splitw(Wf[idx], wfb, wfb + 64 * 136, n * 136 + k);
    }
}

// ================= counting sort of edges by dst =================
__global__ void zero_init(int* __restrict__ hist, int* __restrict__ cursor,
                          float* __restrict__ agg, int N) {
    int i = blockIdx.x * blockDim.x + threadIdx.x;
    if (i < N) { hist[i] = 0; cursor[i] = 0; }
    if (i < N * 32) ((float4*)agg)[i] = make_float4(0.f, 0.f, 0.f, 0.f);
}

__global__ void hist_kernel(const int* __restrict__ dst, int* __restrict__ hist, int E) {
    int e = blockIdx.x * blockDim.x + threadIdx.x;
    if (e < E) atomicAdd(&hist[dst[e]], 1);
}

__global__ void scan1(const int* __restrict__ hist, int* __restrict__ rowptr,
                      int* __restrict__ bsum, int N) {
    __shared__ int s[256];
    int t = threadIdx.x, i = blockIdx.x * 256 + t;
    int v = (i < N) ? hist[i] : 0;
    s[t] = v;
    __syncthreads();
    #pragma unroll
    for (int o = 1; o < 256; o <<= 1) {
        int u = (t >= o) ? s[t - o] : 0;
        __syncthreads();
        s[t] += u;
        __syncthreads();
    }
    if (i < N) rowptr[i] = s[t];
    if (t == 255) bsum[blockIdx.x] = s[255];
}

__global__ void scan2(int* __restrict__ bsum, int nb) {
    __shared__ int s[256];
    int t = threadIdx.x;
    int orig = (t < nb) ? bsum[t] : 0;
    s[t] = orig;
    __syncthreads();
    #pragma unroll
    for (int o = 1; o < 256; o <<= 1) {
        int u = (t >= o) ? s[t - o] : 0;
        __syncthreads();
        s[t] += u;
        __syncthreads();
    }
    if (t < nb) bsum[t] = s[t] - orig;
}

__global__ void scan3(int* __restrict__ rowptr, const int* __restrict__ hist,
                      const int* __restrict__ bsum, int N, int E) {
    int i = blockIdx.x * blockDim.x + threadIdx.x;
    if (i < N) rowptr[i] = rowptr[i] - hist[i] + bsum[i >> 8];
    if (i == N) rowptr[N] = E;
}

__global__ void scatter_kernel(const int* __restrict__ dst, const int* __restrict__ rowptr,
                               int* __restrict__ cursor, int* __restrict__ perm, int E) {
    int e = blockIdx.x * blockDim.x + threadIdx.x;
    if (e < E) {
        int d = dst[e];
        int pos = rowptr[d] + atomicAdd(&cursor[d], 1);
        perm[pos] = e;
    }
}

// ================= tensor-core node GEMM (fp16 2-term) =================
template<int KCH, int NB, bool RELU>
__global__ __launch_bounds__(256) void ngemm(
    const float* __restrict__ A, const uint4* __restrict__ Wt,
    const float* __restrict__ bias, float* __restrict__ C, int M, int Nfull)
{
    constexpr int K = KCH * 16;
    constexpr int KP = K + 8;
    constexpr int NT = NB * 8;
    extern __shared__ char nsm[];
    __half* Whs = (__half*)nsm;
    __half* Wls = Whs + NT * KP;
    float* bs = (float*)(Wls + NT * KP);

    int tid = threadIdx.x;
    int n0 = blockIdx.y * NT;
    {
        const uint4* hsrc = Wt + n0 * KP / 8;
        const uint4* lsrc = Wt + (Nfull * KP) / 8 + n0 * KP / 8;
        uint4* hdst = (uint4*)Whs;
        uint4* ldst = (uint4*)Wls;
        constexpr int CNT = NT * KP / 8;
        for (int i = tid; i < CNT; i += 256) { hdst[i] = hsrc[i]; ldst[i] = lsrc[i]; }
        if (tid < NT) bs[tid] = bias ? bias[n0 + tid] : 0.f;
    }
    __syncthreads();

    int lane = tid & 31, wid = tid >> 5;
    int qr = lane >> 2, qc = (lane & 3) * 2;
    int m0 = (blockIdx.x * 8 + wid) * 16;
    int r0 = m0 + qr, r1 = r0 + 8;
    bool v0 = r0 < M, v1 = r1 < M;
    const float* a0 = A + (size_t)(v0 ? r0 : 0) * K;
    const float* a1 = A + (size_t)(v1 ? r1 : 0) * K;

    float acc[NB][4];
    #pragma unroll
    for (int nb = 0; nb < NB; nb++) {
        acc[nb][0] = acc[nb][1] = acc[nb][2] = acc[nb][3] = 0.f;
    }

    #pragma unroll 2
    for (int j = 0; j < KCH; j++) {
        uint32_t Ah[4];
        float2 x0 = *(const float2*)(a0 + 16 * j + qc);
        float2 x1 = *(const float2*)(a1 + 16 * j + qc);
        float2 x2 = *(const float2*)(a0 + 16 * j + qc + 8);
        float2 x3 = *(const float2*)(a1 + 16 * j + qc + 8);
        Ah[0] = packh(x0.x, x0.y);
        Ah[1] = packh(x1.x, x1.y);
        Ah[2] = packh(x2.x, x2.y);
        Ah[3] = packh(x3.x, x3.y);
        #pragma unroll
        for (int nb = 0; nb < NB; nb++) {
            const __half* ph = Whs + (8 * nb + qr) * KP + 16 * j + qc;
            const __half* pl = Wls + (8 * nb + qr) * KP + 16 * j + qc;
            uint32_t bh0 = *(const uint32_t*)ph;
            uint32_t bh1 = *(const uint32_t*)(ph + 8);
            uint32_t bl0 = *(const uint32_t*)pl;
            uint32_t bl1 = *(const uint32_t*)(pl + 8);
            mma_f16(acc[nb], Ah, bh0, bh1);
            mma_f16(acc[nb], Ah, bl0, bl1);
        }
    }

    #pragma unroll
    for (int nb = 0; nb < NB; nb++) {
        int col = 8 * nb + qc;
        float b0v = bs[col], b1v = bs[col + 1];
        float u0 = acc[nb][0] + b0v, u1 = acc[nb][1] + b1v;
        float u2 = acc[nb][2] + b0v, u3 = acc[nb][3] + b1v;
        if (RELU) {
            u0 = fmaxf(u0, 0.f); u1 = fmaxf(u1, 0.f);
            u2 = fmaxf(u2, 0.f); u3 = fmaxf(u3, 0.f);
        }
        if (v0) *(float2*)(C + (size_t)r0 * Nfull + n0 + col) = make_float2(u0, u1);
        if (v1) *(float2*)(C + (size_t)r1 * Nfull + n0 + col) = make_float2(u2, u3);
    }
}

// ===== mma.sync fused edge kernel (fp16 2-term, M=32 tiles, nb-grouped, 256 thr) =====
#define EDGE3_SMEM (176128 + 1024)
#define EDGE_THREADS 256
#define EDGE_WARPS 8

// one N-group (4 nb) of one stage: acc[4][8] += Ain @ W(nb-group)
template<int NC>
__device__ __forceinline__ void group_mma(
    float acc[4][8], const uint32_t Ain[][8], int grp,
    const __half* __restrict__ Wh, const __half* __restrict__ Wl,
    int KP, int qr, int qc)
{
    #pragma unroll
    for (int i = 0; i < 4; i++)
        #pragma unroll
        for (int q = 0; q < 8; q++) acc[i][q] = 0.f;
    #pragma unroll
    for (int j = 0; j < NC; j++) {
        #pragma unroll
        for (int i = 0; i < 4; i++) {
            int nb = grp * 4 + i;
            const __half* ph = Wh + (8 * nb + qr) * KP + 16 * j + qc;
            const __half* pl = Wl + (8 * nb + qr) * KP + 16 * j + qc;
            uint32_t bh0 = *(const uint32_t*)ph;
            uint32_t bh1 = *(const uint32_t*)(ph + 8);
            uint32_t bl0 = *(const uint32_t*)pl;
            uint32_t bl1 = *(const uint32_t*)(pl + 8);
            mma_f16(acc[i] + 0, Ain[j] + 0, bh0, bh1);
            mma_f16(acc[i] + 0, Ain[j] + 0, bl0, bl1);
            mma_f16(acc[i] + 4, Ain[j] + 4, bh0, bh1);
            mma_f16(acc[i] + 4, Ain[j] + 4, bl0, bl1);
        }
    }
}

__global__ __launch_bounds__(EDGE_THREADS) void edge_kernel8(
    const float* __restrict__ ea,
    const int* __restrict__ src, const int* __restrict__ dst,
    const int* __restrict__ perm,
    const uint4* __restrict__ wpack,
    const float* __restrict__ be1,
    const float* __restrict__ ab, float* __restrict__ agg, int E)
{
    extern __shared__ char smem[];
    __half* W = (__half*)smem;
    float* be1s = (float*)(smem + 176128);

    int tid = threadIdx.x;
    {
        uint4* s4 = (uint4*)smem;
        for (int i = tid; i < 11008; i += EDGE_THREADS) s4[i] = wpack[i];
        if (tid < 128) be1s[tid] = be1[tid];
    }
    __syncthreads();

    const __half* We1h = W + WO_WE1H;
    const __half* We1l = W + WO_WE1L;
    const __half* Wch  = W + WO_WCH;
    const __half* Wcl  = W + WO_WCL;
    const __half* Wm2h = W + WO_WM2H;
    const __half* Wm2l = W + WO_WM2L;

    int lane = tid & 31, wid = tid >> 5;
    int qr = lane >> 2;
    int qc = (lane & 3) * 2;

    int nG = (E + 31) >> 5;
    for (int g = blockIdx.x * EDGE_WARPS + wid; g < nG; g += gridDim.x * EDGE_WARPS) {
        int p0 = g << 5;
        int pr[4] = {p0 + qr, p0 + qr + 8, p0 + qr + 16, p0 + qr + 24};
        bool v[4];
        int ec[4], d[4], s[4];
        #pragma unroll
        for (int r = 0; r < 4; r++) {
            v[r] = pr[r] < E;
            ec[r] = v[r] ? perm[pr[r]] : 0;
            d[r] = dst[ec[r]];
            s[r] = src[ec[r]];
        }

        uint32_t EaF[4][8];   // S1 input
        uint32_t Aa[8][8];    // S1 out / S2 in
        uint32_t Ab[8][8];    // S2 out / S3 in
        float acc[4][8];

        // ---- load ea fragments (K=64, 4 chunks, 4 rows) ----
        #pragma unroll
        for (int j = 0; j < 4; j++) {
            #pragma unroll
            for (int r = 0; r < 4; r++) {
                const float* rp = ea + (size_t)ec[r] * 64 + 16 * j + qc;
                float2 xa = *(const float2*)rp;
                float2 xb = *(const float2*)(rp + 8);
                int base = (r >> 1) * 4 + (r & 1);
                EaF[j][base] = packh(xa.x, xa.y);
                EaF[j][base + 2] = packh(xb.x, xb.y);
            }
        }

        // ---- S1: grouped ----
        #pragma unroll
        for (int grp = 0; grp < 4; grp++) {
            group_mma<4>(acc, EaF, grp, We1h, We1l, 72, qr, qc);
            #pragma unroll
            for (int i = 0; i < 4; i++) {
                int nb = grp * 4 + i;
                int col = 8 * nb + qc;
                float b0 = be1s[col], b1 = be1s[col + 1];
                int j = nb >> 1, q = (nb & 1) * 2;
                Aa[j][q]     = packh(fmaxf(acc[i][0] + b0, 0.f), fmaxf(acc[i][1] + b1, 0.f));
                Aa[j][q + 1] = packh(fmaxf(acc[i][2] + b0, 0.f), fmaxf(acc[i][3] + b1, 0.f));
                Aa[j][q + 4] = packh(fmaxf(acc[i][4] + b0, 0.f), fmaxf(acc[i][5] + b1, 0.f));
                Aa[j][q + 5] = packh(fmaxf(acc[i][6] + b0, 0.f), fmaxf(acc[i][7] + b1, 0.f));
            }
        }

        // ---- S2: grouped (bc folded into ab) ----
        {
            const float* ap0 = ab + (size_t)d[0] * 256;
            const float* ap1 = ab + (size_t)d[1] * 256;
            const float* ap2 = ab + (size_t)d[2] * 256;
            const float* ap3 = ab + (size_t)d[3] * 256;
            const float* bp0 = ab + (size_t)s[0] * 256 + 128;
            const float* bp1 = ab + (size_t)s[1] * 256 + 128;
            const float* bp2 = ab + (size_t)s[2] * 256 + 128;
            const float* bp3 = ab + (size_t)s[3] * 256 + 128;
            #pragma unroll
            for (int grp = 0; grp < 4; grp++) {
                group_mma<8>(acc, Aa, grp, Wch, Wcl, 136, qr, qc);
                #pragma unroll
                for (int i = 0; i < 4; i++) {
                    int nb = grp * 4 + i;
                    int col = 8 * nb + qc;
                    float2 ga0 = *(const float2*)(ap0 + col);
                    float2 gb0 = *(const float2*)(bp0 + col);
                    float2 ga1 = *(const float2*)(ap1 + col);
                    float2 gb1 = *(const float2*)(bp1 + col);
                    float2 ga2 = *(const float2*)(ap2 + col);
                    float2 gb2 = *(const float2*)(bp2 + col);
                    float2 ga3 = *(const float2*)(ap3 + col);
                    float2 gb3 = *(const float2*)(bp3 + col);
                    int j = nb >> 1, q = (nb & 1) * 2;
                    Ab[j][q]     = packh(fmaxf(acc[i][0] + ga0.x + gb0.x, 0.f),
                                         fmaxf(acc[i][1] + ga0.y + gb0.y, 0.f));
                    Ab[j][q + 1] = packh(fmaxf(acc[i][2] + ga1.x + gb1.x, 0.f),
                                         fmaxf(acc[i][3] + ga1.y + gb1.y, 0.f));
                    Ab[j][q + 4] = packh(fmaxf(acc[i][4] + ga2.x + gb2.x, 0.f),
                                         fmaxf(acc[i][5] + ga2.y + gb2.y, 0.f));
                    Ab[j][q + 5] = packh(fmaxf(acc[i][6] + ga3.x + gb3.x, 0.f),
                                         fmaxf(acc[i][7] + ga3.y + gb3.y, 0.f));
                }
            }
        }

        // ---- S3: grouped + deduped scatter (sorted: d[0]<=d[1]<=d[2]<=d[3]) ----
        {
            bool all4 = v[3] && (d[0] == d[3]);
            bool s01 = v[1] && (d[0] == d[1]);
            bool s23 = v[3] && (d[2] == d[3]);
            float* g0 = agg + (size_t)d[0] * 128;
            float* g1 = agg + (size_t)d[1] * 128;
            float* g2 = agg + (size_t)d[2] * 128;
            float* g3 = agg + (size_t)d[3] * 128;
            #pragma unroll
            for (int grp = 0; grp < 4; grp++) {
                group_mma<8>(acc, Ab, grp, Wm2h, Wm2l, 136, qr, qc);
                #pragma unroll
                for (int i = 0; i < 4; i++) {
                    int nb = grp * 4 + i;
                    int col = 8 * nb + qc;
                    // acc[i]: [0,1]=row0, [2,3]=row1, [4,5]=row2, [6,7]=row3
                    if (all4) {
                        asm volatile("red.global.add.v2.f32 [%0], {%1, %2};"
                                     :: "l"(g0 + col),
                                        "f"(acc[i][0] + acc[i][2] + acc[i][4] + acc[i][6]),
                                        "f"(acc[i][1] + acc[i][3] + acc[i][5] + acc[i][7]) : "memory");
                    } else {
                        if (s01) {
                            asm volatile("red.global.add.v2.f32 [%0], {%1, %2};"
                                         :: "l"(g0 + col),
                                            "f"(acc[i][0] + acc[i][2]),
                                            "f"(acc[i][1] + acc[i][3]) : "memory");
                        } else {
                            if (v[0])
                                asm volatile("red.global.add.v2.f32 [%0], {%1, %2};"
                                             :: "l"(g0 + col), "f"(acc[i][0]), "f"(acc[i][1]) : "memory");
                            if (v[1])
                                asm volatile("red.global.add.v2.f32 [%0], {%1, %2};"
                                             :: "l"(g1 + col), "f"(acc[i][2]), "f"(acc[i][3]) : "memory");
                        }
                        if (s23) {
                            asm volatile("red.global.add.v2.f32 [%0], {%1, %2};"
                                         :: "l"(g2 + col),
                                            "f"(acc[i][4] + acc[i][6]),
                                            "f"(acc[i][5] + acc[i][7]) : "memory");
                        } else {
                            if (v[2])
                                asm volatile("red.global.add.v2.f32 [%0], {%1, %2};"
                                             :: "l"(g2 + col), "f"(acc[i][4]), "f"(acc[i][5]) : "memory");
                            if (v[3])
                                asm volatile("red.global.add.v2.f32 [%0], {%1, %2};"
                                             :: "l"(g3 + col), "f"(acc[i][6]), "f"(acc[i][7]) : "memory");
                        }
                    }
                }
            }
        }
    }
}

// ================= LayerNorm + relu (+ agg re-zero) =================
__global__ void ln_kernel(float* __restrict__ agg, const int* __restrict__ rowptr,
                          const float* __restrict__ bm2, const float* __restrict__ lnw,
                          const float* __restrict__ lnb, float* __restrict__ xout, int N)
{
    int node = (blockIdx.x * blockDim.x + threadIdx.x) >> 5;
    int lane = threadIdx.x & 31;
    if (node >= N) return;
    float d = (float)(rowptr[node + 1] - rowptr[node]);
    float inv = 1.f / fmaxf(d, 1.f);
    float add = (d > 0.f) ? 1.f : 0.f;
    float4 v = ((const float4*)agg)[(size_t)node * 32 + lane];
    ((float4*)agg)[(size_t)node * 32 + lane] = make_float4(0.f, 0.f, 0.f, 0.f);
    float4 b = ((const float4*)bm2)[lane];
    v.x = v.x * inv + add * b.x;
    v.y = v.y * inv + add * b.y;
    v.z = v.z * inv + add * b.z;
    v.w = v.w * inv + add * b.w;
    float s = v.x + v.y + v.z + v.w;
    #pragma unroll
    for (int o = 16; o; o >>= 1) s += __shfl_xor_sync(0xffffffffu, s, o);
    float mu = s * (1.f / 128.f);
    float d0 = v.x - mu, d1 = v.y - mu, d2 = v.z - mu, d3 = v.w - mu;
    float q = d0 * d0 + d1 * d1 + d2 * d2 + d3 * d3;
    #pragma unroll
    for (int o = 16; o; o >>= 1) q += __shfl_xor_sync(0xffffffffu, q, o);
    float rs = rsqrtf(q * (1.f / 128.f) + 1e-5f);
    float4 w = ((const float4*)lnw)[lane];
    float4 bb = ((const float4*)lnb)[lane];
    float4 o;
    o.x = fmaxf(d0 * rs * w.x + bb.x, 0.f);
    o.y = fmaxf(d1 * rs * w.y + bb.y, 0.f);
    o.z = fmaxf(d2 * rs * w.z + bb.z, 0.f);
    o.w = fmaxf(d3 * rs * w.w + bb.w, 0.f);
    ((float4*)xout)[(size_t)node * 32 + lane] = o;
}

// ================= host =================
extern "C" void kernel_launch(void* const* d_in, const int* in_sizes, int n_in,
                              void* d_out, int out_size)
{
    const float* x    = (const float*)d_in[0];
    const float* ea   = (const float*)d_in[1];
    const int*   eidx = (const int*)  d_in[2];
    const float* Wn1  = (const float*)d_in[3];
    const float* bn1  = (const float*)d_in[4];
    const float* Wn2  = (const float*)d_in[5];
    const float* bn2  = (const float*)d_in[6];
    const float* We1  = (const float*)d_in[7];
    const float* be1  = (const float*)d_in[8];
    const float* We2  = (const float*)d_in[9];
    const float* be2  = (const float*)d_in[10];
    const float* Wm1  = (const float*)d_in[11];
    const float* bm1  = (const float*)d_in[12];
    const float* Wm2  = (const float*)d_in[13];
    const float* bm2  = (const float*)d_in[14];
    const float* lnw  = (const float*)d_in[15];
    const float* lnb  = (const float*)d_in[16];
    const float* Wf   = (const float*)d_in[17];
    const float* bf   = (const float*)d_in[18];

    int N = in_sizes[0] / 128;
    int E = in_sizes[1] / 64;
    const int* srcp = eidx;
    const int* dstp = eidx + E;

    float *h1n, *ab, *xb, *agg, *Wab, *Wc, *bch;
    int *hist, *cursor, *rowptr, *bsum, *perm;
    uint4 *wpack, *wnode, *wf;
    cudaGetSymbolAddress((void**)&h1n, g_h1n);
    cudaGetSymbolAddress((void**)&ab,  g_ab);
    cudaGetSymbolAddress((void**)&xb,  g_x);
    cudaGetSymbolAddress((void**)&agg, g_agg);
    cudaGetSymbolAddress((void**)&Wab, g_Wab);
    cudaGetSymbolAddress((void**)&Wc,  g_Wc);
    cudaGetSymbolAddress((void**)&bch, g_bch);
    cudaGetSymbolAddress((void**)&hist, g_hist);
    cudaGetSymbolAddress((void**)&cursor, g_cursor);
    cudaGetSymbolAddress((void**)&rowptr, g_rowptr);
    cudaGetSymbolAddress((void**)&bsum, g_bsum);
    cudaGetSymbolAddress((void**)&perm, g_perm);
    cudaGetSymbolAddress((void**)&wpack, g_wpack);
    cudaGetSymbolAddress((void**)&wnode, g_wnode);
    cudaGetSymbolAddress((void**)&wf, g_wf);
    __half* wb = (__half*)wpack;
    __half* nbw = (__half*)wnode;
    __half* wfb = (__half*)wf;

    cudaFuncSetAttribute(edge_kernel8, cudaFuncAttributeMaxDynamicSharedMemorySize,
                         EDGE3_SMEM);
    int smW1  = 2 * 128 * 136 * 2 + 512;
    int smWab = 2 * 128 * 264 * 2 + 512;
    int smWf  = 2 * 64 * 136 * 2 + 256;
    cudaFuncSetAttribute(ngemm<8, 16, true>,   cudaFuncAttributeMaxDynamicSharedMemorySize, smW1);
    cudaFuncSetAttribute(ngemm<16, 16, false>, cudaFuncAttributeMaxDynamicSharedMemorySize, smWab);
    cudaFuncSetAttribute(ngemm<8, 8, false>,   cudaFuncAttributeMaxDynamicSharedMemorySize, smWf);

    int nBlk = (N + 255) / 256;
    zero_init<<<(N * 32 + 255) / 256, 256>>>(hist, cursor, agg, N);
    hist_kernel<<<(E + 255) / 256, 256>>>(dstp, hist, E);
    scan1<<<nBlk, 256>>>(hist, rowptr, bsum, N);
    scan2<<<1, 256>>>(bsum, nBlk);
    scan3<<<(N + 256) / 256, 256>>>(rowptr, hist, bsum, N, E);
    scatter_kernel<<<(E + 255) / 256, 256>>>(dstp, rowptr, cursor, perm, E);
    fuse_all<<<1008, 256>>>(Wn2, Wm1, We2, bn2, be2, bm1, Wab, Wc, bch);
    prep_all<<<1664, 256>>>(We1, Wc, Wm2, Wn1, Wab, Wf, wb, nbw, wfb);

    const float* curx = x;
    int gRows = (N + 127) / 128;
    for (int l = 0; l < LLAYERS; l++) {
        __half* npb = nbw + (size_t)l * NP_LAYER_ELEMS;
        ngemm<8, 16, true><<<dim3(gRows, 2), 256, smW1>>>(
            curx, (const uint4*)(npb + NP_W1), bn1 + l * 256, h1n, N, 256);
        ngemm<16, 16, false><<<dim3(gRows, 2), 256, smWab>>>(
            h1n, (const uint4*)(npb + NP_WAB), bch + l * 256, ab, N, 256);
        edge_kernel8<<<148, EDGE_THREADS, EDGE3_SMEM>>>(
            ea, srcp, dstp, perm,
            (const uint4*)(wb + (size_t)l * WP_LAYER_ELEMS),
            be1 + l * 128, ab, agg, E);
        ln_kernel<<<(N + 7) / 8, 256>>>(agg, rowptr, bm2 + l * 128, lnw + l * 128,
                                        lnb + l * 128, xb, N);
        curx = xb;
    }
    ngemm<8, 8, false><<<dim3(gRows, 1), 256, smWf>>>(
        curx, (const uint4*)wfb, bf, (float*)d_out, N, 64);
}

// round 15
// speedup vs baseline: 1.4699x; 1.4699x over previous
#include <cuda_runtime.h>
#include <cuda_bf16.h>
#include <cuda_fp16.h>
#include <cstdint>

#define MAXN 50000
#define MAXE 800000
#define LLAYERS 3

// ================= helpers =================
// pack two floats to half2: hi_v -> upper 16, lo_v -> lower 16
__device__ __forceinline__ uint32_t packh(float lo_v, float hi_v) {
    uint32_t r;
    asm("cvt.rn.f16x2.f32 %0, %1, %2;" : "=r"(r) : "f"(hi_v), "f"(lo_v));
    return r;
}

__device__ __forceinline__ void mma_f16(float* c, const uint32_t* a, uint32_t b0, uint32_t b1) {
    asm volatile(
        "mma.sync.aligned.m16n8k16.row.col.f32.f16.f16.f32 "
        "{%0,%1,%2,%3}, {%4,%5,%6,%7}, {%8,%9}, {%0,%1,%2,%3};\n"
        : "+f"(c[0]), "+f"(c[1]), "+f"(c[2]), "+f"(c[3])
        : "r"(a[0]), "r"(a[1]), "r"(a[2]), "r"(a[3]), "r"(b0), "r"(b1));
}

// ================= scratch (static device globals) =================
__device__ float g_h1n[MAXN * 256];
__device__ float g_ab [MAXN * 256];
__device__ float g_x  [MAXN * 128];
__device__ float g_agg[MAXN * 128];
__device__ float g_Wab [LLAYERS * 256 * 256];
__device__ float g_Wc  [LLAYERS * 128 * 128];
__device__ float g_bch [LLAYERS * 256];
// sorted-edge machinery
__device__ int g_hist[MAXN];
__device__ int g_cursor[MAXN];
__device__ int g_rowptr[MAXN + 1];
__device__ int g_bsum[256];
__device__ int g_perm[MAXE];
// per-layer packed fp16 transposed edge weights, 88064 elems / layer
#define WP_LAYER_ELEMS 88064
__device__ uint4 g_wpack[LLAYERS * WP_LAYER_ELEMS * 2 / 16];
// per-layer node weights: [W1hi 256x136][W1lo][WABhi 256x264][WABlo]
#define NP_LAYER_ELEMS 204800
#define NP_W1  0
#define NP_WAB 69632
__device__ uint4 g_wnode[LLAYERS * NP_LAYER_ELEMS * 2 / 16];
__device__ uint4 g_wf[2 * 64 * 136 * 2 / 16];

#define WO_WE1H 0
#define WO_WE1L 9216
#define WO_WCH  18432
#define WO_WCL  35840
#define WO_WM2H 53248
#define WO_WM2L 70656

// ================= fused weight-fuse kernel =================
__global__ __launch_bounds__(256) void fuse_all(
    const float* __restrict__ Wn2, const float* __restrict__ Wm1,
    const float* __restrict__ We2, const float* __restrict__ bn2,
    const float* __restrict__ be2, const float* __restrict__ bm1,
    float* __restrict__ Wab, float* __restrict__ Wc, float* __restrict__ bch)
{
    int b = blockIdx.x, tid = threadIdx.x;
    if (b < 768) {
        int l = b >> 8;
        int idx = (b & 255) * 256 + tid;
        const float* wn2 = Wn2 + (size_t)l * 256 * 128;
        const float* wm1 = Wm1 + (size_t)l * 320 * 128;
        int k = idx >> 8, j = idx & 255;
        const float* wm = (j < 128) ? (wm1 + j) : (wm1 + 128 * 128 + (j - 128));
        float acc = 0.f;
        #pragma unroll 4
        for (int t = 0; t < 128; t++) acc += wn2[k * 128 + t] * wm[t * 128];
        Wab[(size_t)l * 65536 + idx] = acc;
    } else if (b < 960) {
        int lb = b - 768;
        int l = lb / 64;
        int idx = (lb % 64) * 256 + tid;
        const float* we2 = We2 + (size_t)l * 128 * 64;
        const float* wm1 = Wm1 + (size_t)l * 320 * 128;
        int k = idx >> 7, j = idx & 127;
        float acc = 0.f;
        #pragma unroll 4
        for (int t = 0; t < 64; t++) acc += we2[k * 64 + t] * wm1[(256 + t) * 128 + j];
        Wc[(size_t)l * 16384 + idx] = acc;
    } else {
        int lb = b - 960;
        int l = lb / 16;
        int lane = tid & 31;
        int j = (lb % 16) * 8 + (tid >> 5);
        const float* wm1 = Wm1 + (size_t)l * 320 * 128;
        const float* bn2l = bn2 + l * 128;
        const float* be2l = be2 + l * 64;
        float acc = 0.f;
        #pragma unroll
        for (int k = lane; k < 128; k += 32)
            acc += bn2l[k] * (wm1[k * 128 + j] + wm1[(128 + k) * 128 + j]);
        #pragma unroll
        for (int t = lane; t < 64; t += 32)
            acc += be2l[t] * wm1[(256 + t) * 128 + j];
        #pragma unroll
        for (int o = 16; o; o >>= 1) acc += __shfl_xor_sync(0xffffffffu, acc, o);
        if (lane == 0) {
            float half = 0.5f * (bm1[l * 128 + j] + acc);
            bch[l * 256 + j] = half;
            bch[l * 256 + 128 + j] = half;
        }
    }
}

// ================= fused fp16 hi/lo transpose prep kernel =================
__device__ __forceinline__ void splitw(float w, __half* hi, __half* lo, int o) {
    __half h = __float2half_rn(w);
    hi[o] = h;
    lo[o] = __float2half_rn(w - __half2float(h));
}

__global__ __launch_bounds__(256) void prep_all(
    const float* __restrict__ We1, const float* __restrict__ WcG,
    const float* __restrict__ Wm2, const float* __restrict__ Wn1,
    const float* __restrict__ WabG, const float* __restrict__ Wf,
    __half* __restrict__ wb, __half* __restrict__ nbw,
    __half* __restrict__ wfb)
{
    int b = blockIdx.x, tid = threadIdx.x;
    if (b < 96) {
        int l = b / 32;
        int idx = (b % 32) * 256 + tid;
        int n = idx >> 6, k = idx & 63;
        float w = We1[(size_t)l * 8192 + k * 128 + n];
        __half* base = wb + (size_t)l * WP_LAYER_ELEMS;
        splitw(w, base + WO_WE1H, base + WO_WE1L, n * 72 + k);
    } else if (b < 288) {
        int lb = b - 96;
        int l = lb / 64;
        int idx = (lb % 64) * 256 + tid;
        int n = idx >> 7, k = idx & 127;
        float w = WcG[(size_t)l * 16384 + k * 128 + n];
        __half* base = wb + (size_t)l * WP_LAYER_ELEMS;
        splitw(w, base + WO_WCH, base + WO_WCL, n * 136 + k);
    } else if (b < 480) {
        int lb = b - 288;
        int l = lb / 64;
        int idx = (lb % 64) * 256 + tid;
        int n = idx >> 7, k = idx & 127;
        float w = Wm2[(size_t)l * 16384 + k * 128 + n];
        __half* base = wb + (size_t)l * WP_LAYER_ELEMS;
        splitw(w, base + WO_WM2H, base + WO_WM2L, n * 136 + k);
    } else if (b < 864) {
        int lb = b - 480;
        int l = lb / 128;
        int idx = (lb % 128) * 256 + tid;
        int n = idx & 255, k = idx >> 8;
        float w = Wn1[(size_t)l * 32768 + idx];
        __half* base = nbw + (size_t)l * NP_LAYER_ELEMS + NP_W1;
        splitw(w, base, base + 256 * 136, n * 136 + k);
    } else if (b < 1632) {
        int lb = b - 864;
        int l = lb / 256;
        int idx = (lb % 256) * 256 + tid;
        int n = idx & 255, k = idx >> 8;
        float w = WabG[(size_t)l * 65536 + idx];
        __half* base = nbw + (size_t)l * NP_LAYER_ELEMS + NP_WAB;
        splitw(w, base, base + 256 * 264, n * 264 + k);
    } else {
        int idx = (b - 1632) * 256 + tid;
        int n = idx & 63, k = idx >> 6;
        splitw(Wf[idx], wfb, wfb + 64 * 136, n * 136 + k);
    }
}

// ================= counting sort of edges by dst =================
__global__ void zero_init(int* __restrict__ hist, int* __restrict__ cursor,
                          float* __restrict__ agg, int N) {
    int i = blockIdx.x * blockDim.x + threadIdx.x;
    if (i < N) { hist[i] = 0; cursor[i] = 0; }
    if (i < N * 32) ((float4*)agg)[i] = make_float4(0.f, 0.f, 0.f, 0.f);
}

__global__ void hist_kernel(const int* __restrict__ dst, int* __restrict__ hist, int E) {
    int e = blockIdx.x * blockDim.x + threadIdx.x;
    if (e < E) atomicAdd(&hist[dst[e]], 1);
}

__global__ void scan1(const int* __restrict__ hist, int* __restrict__ rowptr,
                      int* __restrict__ bsum, int N) {
    __shared__ int s[256];
    int t = threadIdx.x, i = blockIdx.x * 256 + t;
    int v = (i < N) ? hist[i] : 0;
    s[t] = v;
    __syncthreads();
    #pragma unroll
    for (int o = 1; o < 256; o <<= 1) {
        int u = (t >= o) ? s[t - o] : 0;
        __syncthreads();
        s[t] += u;
        __syncthreads();
    }
    if (i < N) rowptr[i] = s[t];
    if (t == 255) bsum[blockIdx.x] = s[255];
}

__global__ void scan2(int* __restrict__ bsum, int nb) {
    __shared__ int s[256];
    int t = threadIdx.x;
    int orig = (t < nb) ? bsum[t] : 0;
    s[t] = orig;
    __syncthreads();
    #pragma unroll
    for (int o = 1; o < 256; o <<= 1) {
        int u = (t >= o) ? s[t - o] : 0;
        __syncthreads();
        s[t] += u;
        __syncthreads();
    }
    if (t < nb) bsum[t] = s[t] - orig;
}

__global__ void scan3(int* __restrict__ rowptr, const int* __restrict__ hist,
                      const int* __restrict__ bsum, int N, int E) {
    int i = blockIdx.x * blockDim.x + threadIdx.x;
    if (i < N) rowptr[i] = rowptr[i] - hist[i] + bsum[i >> 8];
    if (i == N) rowptr[N] = E;
}

__global__ void scatter_kernel(const int* __restrict__ dst, const int* __restrict__ rowptr,
                               int* __restrict__ cursor, int* __restrict__ perm, int E) {
    int e = blockIdx.x * blockDim.x + threadIdx.x;
    if (e < E) {
        int d = dst[e];
        int pos = rowptr[d] + atomicAdd(&cursor[d], 1);
        perm[pos] = e;
    }
}

// ========== tensor-core node GEMM (fp16 2-term, PERSISTENT over row-blocks) ==========
template<int KCH, int NB, bool RELU>
__global__ __launch_bounds__(256) void ngemm(
    const float* __restrict__ A, const uint4* __restrict__ Wt,
    const float* __restrict__ bias, float* __restrict__ C, int M, int Nfull)
{
    constexpr int K = KCH * 16;
    constexpr int KP = K + 8;
    constexpr int NT = NB * 8;
    extern __shared__ char nsm[];
    __half* Whs = (__half*)nsm;
    __half* Wls = Whs + NT * KP;
    float* bs = (float*)(Wls + NT * KP);

    int tid = threadIdx.x;
    int n0 = blockIdx.y * NT;
    {
        const uint4* hsrc = Wt + n0 * KP / 8;
        const uint4* lsrc = Wt + (Nfull * KP) / 8 + n0 * KP / 8;
        uint4* hdst = (uint4*)Whs;
        uint4* ldst = (uint4*)Wls;
        constexpr int CNT = NT * KP / 8;
        for (int i = tid; i < CNT; i += 256) { hdst[i] = hsrc[i]; ldst[i] = lsrc[i]; }
        if (tid < NT) bs[tid] = bias ? bias[n0 + tid] : 0.f;
    }
    __syncthreads();

    int lane = tid & 31, wid = tid >> 5;
    int qr = lane >> 2, qc = (lane & 3) * 2;

    int nMB = (M + 127) >> 7;   // 128 rows per CTA-iteration (8 warps x 16)
    for (int mb = blockIdx.x; mb < nMB; mb += gridDim.x) {
        int m0 = (mb * 8 + wid) * 16;
        int r0 = m0 + qr, r1 = r0 + 8;
        bool v0 = r0 < M, v1 = r1 < M;
        const float* a0 = A + (size_t)(v0 ? r0 : 0) * K;
        const float* a1 = A + (size_t)(v1 ? r1 : 0) * K;

        float acc[NB][4];
        #pragma unroll
        for (int nb = 0; nb < NB; nb++) {
            acc[nb][0] = acc[nb][1] = acc[nb][2] = acc[nb][3] = 0.f;
        }

        #pragma unroll 2
        for (int j = 0; j < KCH; j++) {
            uint32_t Ah[4];
            float2 x0 = *(const float2*)(a0 + 16 * j + qc);
            float2 x1 = *(const float2*)(a1 + 16 * j + qc);
            float2 x2 = *(const float2*)(a0 + 16 * j + qc + 8);
            float2 x3 = *(const float2*)(a1 + 16 * j + qc + 8);
            Ah[0] = packh(x0.x, x0.y);
            Ah[1] = packh(x1.x, x1.y);
            Ah[2] = packh(x2.x, x2.y);
            Ah[3] = packh(x3.x, x3.y);
            #pragma unroll
            for (int nb = 0; nb < NB; nb++) {
                const __half* ph = Whs + (8 * nb + qr) * KP + 16 * j + qc;
                const __half* pl = Wls + (8 * nb + qr) * KP + 16 * j + qc;
                uint32_t bh0 = *(const uint32_t*)ph;
                uint32_t bh1 = *(const uint32_t*)(ph + 8);
                uint32_t bl0 = *(const uint32_t*)pl;
                uint32_t bl1 = *(const uint32_t*)(pl + 8);
                mma_f16(acc[nb], Ah, bh0, bh1);
                mma_f16(acc[nb], Ah, bl0, bl1);
            }
        }

        #pragma unroll
        for (int nb = 0; nb < NB; nb++) {
            int col = 8 * nb + qc;
            float b0v = bs[col], b1v = bs[col + 1];
            float u0 = acc[nb][0] + b0v, u1 = acc[nb][1] + b1v;
            float u2 = acc[nb][2] + b0v, u3 = acc[nb][3] + b1v;
            if (RELU) {
                u0 = fmaxf(u0, 0.f); u1 = fmaxf(u1, 0.f);
                u2 = fmaxf(u2, 0.f); u3 = fmaxf(u3, 0.f);
            }
            if (v0) *(float2*)(C + (size_t)r0 * Nfull + n0 + col) = make_float2(u0, u1);
            if (v1) *(float2*)(C + (size_t)r1 * Nfull + n0 + col) = make_float2(u2, u3);
        }
    }
}

// ===== mma.sync fused edge kernel (fp16 2-term, M=16, 384 threads — R12 exact) =====
#define EDGE3_SMEM (176128 + 1024)
#define EDGE_THREADS 384
#define EDGE_WARPS 12

template<int NC>
__device__ __forceinline__ void stage_mma(
    float acc[16][4], const uint32_t Ah[8][4],
    const __half* __restrict__ Wh, const __half* __restrict__ Wl,
    int KP, int qr, int qc)
{
    #pragma unroll
    for (int j = 0; j < NC; j++) {
        #pragma unroll
        for (int nb = 0; nb < 16; nb++) {
            const __half* ph = Wh + (8 * nb + qr) * KP + 16 * j + qc;
            const __half* pl = Wl + (8 * nb + qr) * KP + 16 * j + qc;
            uint32_t bh0 = *(const uint32_t*)ph;
            uint32_t bh1 = *(const uint32_t*)(ph + 8);
            uint32_t bl0 = *(const uint32_t*)pl;
            uint32_t bl1 = *(const uint32_t*)(pl + 8);
            mma_f16(acc[nb], Ah[j], bh0, bh1);
            mma_f16(acc[nb], Ah[j], bl0, bl1);
        }
    }
}

__global__ __launch_bounds__(EDGE_THREADS, 1) void edge_kernel6(
    const float* __restrict__ ea,
    const int* __restrict__ src, const int* __restrict__ dst,
    const int* __restrict__ perm,
    const uint4* __restrict__ wpack,
    const float* __restrict__ be1,
    const float* __restrict__ ab, float* __restrict__ agg, int E)
{
    extern __shared__ char smem[];
    __half* W = (__half*)smem;
    float* be1s = (float*)(smem + 176128);

    int tid = threadIdx.x;
    {
        uint4* s4 = (uint4*)smem;
        for (int i = tid; i < 11008; i += EDGE_THREADS) s4[i] = wpack[i];
        if (tid < 128) be1s[tid] = be1[tid];
    }
    __syncthreads();

    const __half* We1h = W + WO_WE1H;
    const __half* We1l = W + WO_WE1L;
    const __half* Wch  = W + WO_WCH;
    const __half* Wcl  = W + WO_WCL;
    const __half* Wm2h = W + WO_WM2H;
    const __half* Wm2l = W + WO_WM2L;

    int lane = tid & 31, wid = tid >> 5;
    int qr = lane >> 2;
    int qc = (lane & 3) * 2;

    int nG = (E + 15) >> 4;
    for (int g = blockIdx.x * EDGE_WARPS + wid; g < nG; g += gridDim.x * EDGE_WARPS) {
        int p0 = g << 4;
        int pr0 = p0 + qr, pr1 = pr0 + 8;
        bool v0 = pr0 < E, v1 = pr1 < E;
        int ec0 = v0 ? perm[pr0] : 0, ec1 = v1 ? perm[pr1] : 0;
        int d0 = dst[ec0], d1 = dst[ec1];
        int s0 = src[ec0], s1 = src[ec1];

        uint32_t Ah[8][4];
        float acc[16][4];

        #pragma unroll
        for (int j = 0; j < 4; j++) {
            const float* r0p = ea + (size_t)ec0 * 64 + 16 * j + qc;
            const float* r1p = ea + (size_t)ec1 * 64 + 16 * j + qc;
            float2 x0 = *(const float2*)r0p;
            float2 x1 = *(const float2*)r1p;
            float2 x2 = *(const float2*)(r0p + 8);
            float2 x3 = *(const float2*)(r1p + 8);
            Ah[j][0] = packh(x0.x, x0.y);
            Ah[j][1] = packh(x1.x, x1.y);
            Ah[j][2] = packh(x2.x, x2.y);
            Ah[j][3] = packh(x3.x, x3.y);
        }

        // S1
        #pragma unroll
        for (int nb = 0; nb < 16; nb++)
            #pragma unroll
            for (int q = 0; q < 4; q++) acc[nb][q] = 0.f;
        stage_mma<4>(acc, Ah, We1h, We1l, 72, qr, qc);
        #pragma unroll
        for (int nb = 0; nb < 16; nb++) {
            int col = 8 * nb + qc;
            float b0 = be1s[col], b1 = be1s[col + 1];
            float u0 = fmaxf(acc[nb][0] + b0, 0.f);
            float u1 = fmaxf(acc[nb][1] + b1, 0.f);
            float u2 = fmaxf(acc[nb][2] + b0, 0.f);
            float u3 = fmaxf(acc[nb][3] + b1, 0.f);
            int j = nb >> 1, q = (nb & 1) * 2;
            Ah[j][q]     = packh(u0, u1);
            Ah[j][q + 1] = packh(u2, u3);
        }

        // S2  (bc folded into ab via bch bias in the WAB gemm)
        #pragma unroll
        for (int nb = 0; nb < 16; nb++)
            #pragma unroll
            for (int q = 0; q < 4; q++) acc[nb][q] = 0.f;
        stage_mma<8>(acc, Ah, Wch, Wcl, 136, qr, qc);
        {
            const float* a0p = ab + (size_t)d0 * 256;
            const float* a1p = ab + (size_t)d1 * 256;
            const float* b0p = ab + (size_t)s0 * 256 + 128;
            const float* b1p = ab + (size_t)s1 * 256 + 128;
            #pragma unroll
            for (int nb = 0; nb < 16; nb++) {
                int col = 8 * nb + qc;
                float2 ga0 = *(const float2*)(a0p + col);
                float2 ga1 = *(const float2*)(a1p + col);
                float2 gb0 = *(const float2*)(b0p + col);
                float2 gb1 = *(const float2*)(b1p + col);
                float u0 = fmaxf(acc[nb][0] + ga0.x + gb0.x, 0.f);
                float u1 = fmaxf(acc[nb][1] + ga0.y + gb0.y, 0.f);
                float u2 = fmaxf(acc[nb][2] + ga1.x + gb1.x, 0.f);
                float u3 = fmaxf(acc[nb][3] + ga1.y + gb1.y, 0.f);
                int j = nb >> 1, q = (nb & 1) * 2;
                Ah[j][q]     = packh(u0, u1);
                Ah[j][q + 1] = packh(u2, u3);
            }
        }

        // S3 + deduped atomic scatter (sorted dst => rows qr and qr+8 often share dst)
        #pragma unroll
        for (int nb = 0; nb < 16; nb++)
            #pragma unroll
            for (int q = 0; q < 4; q++) acc[nb][q] = 0.f;
        stage_mma<8>(acc, Ah, Wm2h, Wm2l, 136, qr, qc);
        {
            float* g0 = agg + (size_t)d0 * 128;
            float* g1 = agg + (size_t)d1 * 128;
            bool same = v1 && (d0 == d1);
            #pragma unroll
            for (int nb = 0; nb < 16; nb++) {
                int col = 8 * nb + qc;
                if (same) {
                    asm volatile("red.global.add.v2.f32 [%0], {%1, %2};"
                                 :: "l"(g0 + col),
                                    "f"(acc[nb][0] + acc[nb][2]),
                                    "f"(acc[nb][1] + acc[nb][3]) : "memory");
                } else {
                    if (v0)
                        asm volatile("red.global.add.v2.f32 [%0], {%1, %2};"
                                     :: "l"(g0 + col), "f"(acc[nb][0]), "f"(acc[nb][1]) : "memory");
                    if (v1)
                        asm volatile("red.global.add.v2.f32 [%0], {%1, %2};"
                                     :: "l"(g1 + col), "f"(acc[nb][2]), "f"(acc[nb][3]) : "memory");
                }
            }
        }
    }
}

// ================= LayerNorm + relu (+ agg re-zero) =================
__global__ void ln_kernel(float* __restrict__ agg, const int* __restrict__ rowptr,
                          const float* __restrict__ bm2, const float* __restrict__ lnw,
                          const float* __restrict__ lnb, float* __restrict__ xout, int N)
{
    int node = (blockIdx.x * blockDim.x + threadIdx.x) >> 5;
    int lane = threadIdx.x & 31;
    if (node >= N) return;
    float d = (float)(rowptr[node + 1] - rowptr[node]);
    float inv = 1.f / fmaxf(d, 1.f);
    float add = (d > 0.f) ? 1.f : 0.f;
    float4 v = ((const float4*)agg)[(size_t)node * 32 + lane];
    ((float4*)agg)[(size_t)node * 32 + lane] = make_float4(0.f, 0.f, 0.f, 0.f);
    float4 b = ((const float4*)bm2)[lane];
    v.x = v.x * inv + add * b.x;
    v.y = v.y * inv + add * b.y;
    v.z = v.z * inv + add * b.z;
    v.w = v.w * inv + add * b.w;
    float s = v.x + v.y + v.z + v.w;
    #pragma unroll
    for (int o = 16; o; o >>= 1) s += __shfl_xor_sync(0xffffffffu, s, o);
    float mu = s * (1.f / 128.f);
    float d0 = v.x - mu, d1 = v.y - mu, d2 = v.z - mu, d3 = v.w - mu;
    float q = d0 * d0 + d1 * d1 + d2 * d2 + d3 * d3;
    #pragma unroll
    for (int o = 16; o; o >>= 1) q += __shfl_xor_sync(0xffffffffu, q, o);
    float rs = rsqrtf(q * (1.f / 128.f) + 1e-5f);
    float4 w = ((const float4*)lnw)[lane];
    float4 bb = ((const float4*)lnb)[lane];
    float4 o;
    o.x = fmaxf(d0 * rs * w.x + bb.x, 0.f);
    o.y = fmaxf(d1 * rs * w.y + bb.y, 0.f);
    o.z = fmaxf(d2 * rs * w.z + bb.z, 0.f);
    o.w = fmaxf(d3 * rs * w.w + bb.w, 0.f);
    ((float4*)xout)[(size_t)node * 32 + lane] = o;
}

// ================= host =================
extern "C" void kernel_launch(void* const* d_in, const int* in_sizes, int n_in,
                              void* d_out, int out_size)
{
    const float* x    = (const float*)d_in[0];
    const float* ea   = (const float*)d_in[1];
    const int*   eidx = (const int*)  d_in[2];
    const float* Wn1  = (const float*)d_in[3];
    const float* bn1  = (const float*)d_in[4];
    const float* Wn2  = (const float*)d_in[5];
    const float* bn2  = (const float*)d_in[6];
    const float* We1  = (const float*)d_in[7];
    const float* be1  = (const float*)d_in[8];
    const float* We2  = (const float*)d_in[9];
    const float* be2  = (const float*)d_in[10];
    const float* Wm1  = (const float*)d_in[11];
    const float* bm1  = (const float*)d_in[12];
    const float* Wm2  = (const float*)d_in[13];
    const float* bm2  = (const float*)d_in[14];
    const float* lnw  = (const float*)d_in[15];
    const float* lnb  = (const float*)d_in[16];
    const float* Wf   = (const float*)d_in[17];
    const float* bf   = (const float*)d_in[18];

    int N = in_sizes[0] / 128;
    int E = in_sizes[1] / 64;
    const int* srcp = eidx;
    const int* dstp = eidx + E;

    float *h1n, *ab, *xb, *agg, *Wab, *Wc, *bch;
    int *hist, *cursor, *rowptr, *bsum, *perm;
    uint4 *wpack, *wnode, *wf;
    cudaGetSymbolAddress((void**)&h1n, g_h1n);
    cudaGetSymbolAddress((void**)&ab,  g_ab);
    cudaGetSymbolAddress((void**)&xb,  g_x);
    cudaGetSymbolAddress((void**)&agg, g_agg);
    cudaGetSymbolAddress((void**)&Wab, g_Wab);
    cudaGetSymbolAddress((void**)&Wc,  g_Wc);
    cudaGetSymbolAddress((void**)&bch, g_bch);
    cudaGetSymbolAddress((void**)&hist, g_hist);
    cudaGetSymbolAddress((void**)&cursor, g_cursor);
    cudaGetSymbolAddress((void**)&rowptr, g_rowptr);
    cudaGetSymbolAddress((void**)&bsum, g_bsum);
    cudaGetSymbolAddress((void**)&perm, g_perm);
    cudaGetSymbolAddress((void**)&wpack, g_wpack);
    cudaGetSymbolAddress((void**)&wnode, g_wnode);
    cudaGetSymbolAddress((void**)&wf, g_wf);
    __half* wb = (__half*)wpack;
    __half* nbw = (__half*)wnode;
    __half* wfb = (__half*)wf;

    cudaFuncSetAttribute(edge_kernel6, cudaFuncAttributeMaxDynamicSharedMemorySize,
                         EDGE3_SMEM);
    int smW1  = 2 * 128 * 136 * 2 + 512;   // ngemm<8,16>
    int smWab = 2 * 128 * 264 * 2 + 512;   // ngemm<16,16>
    int smWf  = 2 * 64 * 136 * 2 + 256;    // ngemm<8,8>
    cudaFuncSetAttribute(ngemm<8, 16, true>,   cudaFuncAttributeMaxDynamicSharedMemorySize, smW1);
    cudaFuncSetAttribute(ngemm<16, 16, false>, cudaFuncAttributeMaxDynamicSharedMemorySize, smWab);
    cudaFuncSetAttribute(ngemm<8, 8, false>,   cudaFuncAttributeMaxDynamicSharedMemorySize, smWf);

    int nBlk = (N + 255) / 256;
    zero_init<<<(N * 32 + 255) / 256, 256>>>(hist, cursor, agg, N);
    hist_kernel<<<(E + 255) / 256, 256>>>(dstp, hist, E);
    scan1<<<nBlk, 256>>>(hist, rowptr, bsum, N);
    scan2<<<1, 256>>>(bsum, nBlk);
    scan3<<<(N + 256) / 256, 256>>>(rowptr, hist, bsum, N, E);
    scatter_kernel<<<(E + 255) / 256, 256>>>(dstp, rowptr, cursor, perm, E);
    fuse_all<<<1008, 256>>>(Wn2, Wm1, We2, bn2, be2, bm1, Wab, Wc, bch);
    prep_all<<<1664, 256>>>(We1, Wc, Wm2, Wn1, Wab, Wf, wb, nbw, wfb);

    const float* curx = x;
    for (int l = 0; l < LLAYERS; l++) {
        __half* npb = nbw + (size_t)l * NP_LAYER_ELEMS;
        ngemm<8, 16, true><<<dim3(74, 2), 256, smW1>>>(
            curx, (const uint4*)(npb + NP_W1), bn1 + l * 256, h1n, N, 256);
        ngemm<16, 16, false><<<dim3(74, 2), 256, smWab>>>(
            h1n, (const uint4*)(npb + NP_WAB), bch + l * 256, ab, N, 256);
        edge_kernel6<<<148, EDGE_THREADS, EDGE3_SMEM>>>(
            ea, srcp, dstp, perm,
            (const uint4*)(wb + (size_t)l * WP_LAYER_ELEMS),
            be1 + l * 128, ab, agg, E);
        ln_kernel<<<(N + 7) / 8, 256>>>(agg, rowptr, bm2 + l * 128, lnw + l * 128,
                                        lnb + l * 128, xb, N);
        curx = xb;
    }
    ngemm<8, 8, false><<<dim3(148, 1), 256, smWf>>>(
        curx, (const uint4*)wfb, bf, (float*)d_out, N, 64);
}

// round 16
// speedup vs baseline: 1.8902x; 1.2859x over previous
#include <cuda_runtime.h>
#include <cuda_bf16.h>
#include <cuda_fp16.h>
#include <cstdint>

#define MAXN 50000
#define MAXE 800000
#define LLAYERS 3

// ================= helpers =================
// pack two floats to half2: hi_v -> upper 16, lo_v -> lower 16
__device__ __forceinline__ uint32_t packh(float lo_v, float hi_v) {
    uint32_t r;
    asm("cvt.rn.f16x2.f32 %0, %1, %2;" : "=r"(r) : "f"(hi_v), "f"(lo_v));
    return r;
}

__device__ __forceinline__ void mma_f16(float* c, const uint32_t* a, uint32_t b0, uint32_t b1) {
    asm volatile(
        "mma.sync.aligned.m16n8k16.row.col.f32.f16.f16.f32 "
        "{%0,%1,%2,%3}, {%4,%5,%6,%7}, {%8,%9}, {%0,%1,%2,%3};\n"
        : "+f"(c[0]), "+f"(c[1]), "+f"(c[2]), "+f"(c[3])
        : "r"(a[0]), "r"(a[1]), "r"(a[2]), "r"(a[3]), "r"(b0), "r"(b1));
}

// ================= scratch (static device globals) =================
__device__ float g_h1n[MAXN * 256];
__device__ float g_ab [MAXN * 256];
__device__ float g_x  [MAXN * 128];
__device__ float g_agg[MAXN * 128];
__device__ float g_Wab [LLAYERS * 256 * 256];
__device__ float g_Wc  [LLAYERS * 128 * 128];
__device__ float g_bch [LLAYERS * 256];
// sorted-edge machinery
__device__ int g_hist[MAXN];
__device__ int g_cursor[MAXN];
__device__ int g_rowptr[MAXN + 1];
__device__ int g_bsum[256];
__device__ int g_perm[MAXE];
// per-layer packed fp16 transposed edge weights (hi only), 44032 elems / layer:
// [We1h 128x72][Wch 128x136][Wm2h 128x136]
#define WP_LAYER_ELEMS 44032
__device__ uint4 g_wpack[LLAYERS * WP_LAYER_ELEMS * 2 / 16];
// per-layer node weights: [W1hi 256x136][W1lo][WABhi 256x264][WABlo]
#define NP_LAYER_ELEMS 204800
#define NP_W1  0
#define NP_WAB 69632
__device__ uint4 g_wnode[LLAYERS * NP_LAYER_ELEMS * 2 / 16];
__device__ uint4 g_wf[2 * 64 * 136 * 2 / 16];

#define WO_WE1H 0
#define WO_WCH  9216
#define WO_WM2H 26624

// ================= fused weight-fuse kernel =================
__global__ __launch_bounds__(256) void fuse_all(
    const float* __restrict__ Wn2, const float* __restrict__ Wm1,
    const float* __restrict__ We2, const float* __restrict__ bn2,
    const float* __restrict__ be2, const float* __restrict__ bm1,
    float* __restrict__ Wab, float* __restrict__ Wc, float* __restrict__ bch)
{
    int b = blockIdx.x, tid = threadIdx.x;
    if (b < 768) {
        int l = b >> 8;
        int idx = (b & 255) * 256 + tid;
        const float* wn2 = Wn2 + (size_t)l * 256 * 128;
        const float* wm1 = Wm1 + (size_t)l * 320 * 128;
        int k = idx >> 8, j = idx & 255;
        const float* wm = (j < 128) ? (wm1 + j) : (wm1 + 128 * 128 + (j - 128));
        float acc = 0.f;
        #pragma unroll 4
        for (int t = 0; t < 128; t++) acc += wn2[k * 128 + t] * wm[t * 128];
        Wab[(size_t)l * 65536 + idx] = acc;
    } else if (b < 960) {
        int lb = b - 768;
        int l = lb / 64;
        int idx = (lb % 64) * 256 + tid;
        const float* we2 = We2 + (size_t)l * 128 * 64;
        const float* wm1 = Wm1 + (size_t)l * 320 * 128;
        int k = idx >> 7, j = idx & 127;
        float acc = 0.f;
        #pragma unroll 4
        for (int t = 0; t < 64; t++) acc += we2[k * 64 + t] * wm1[(256 + t) * 128 + j];
        Wc[(size_t)l * 16384 + idx] = acc;
    } else {
        int lb = b - 960;
        int l = lb / 16;
        int lane = tid & 31;
        int j = (lb % 16) * 8 + (tid >> 5);
        const float* wm1 = Wm1 + (size_t)l * 320 * 128;
        const float* bn2l = bn2 + l * 128;
        const float* be2l = be2 + l * 64;
        float acc = 0.f;
        #pragma unroll
        for (int k = lane; k < 128; k += 32)
            acc += bn2l[k] * (wm1[k * 128 + j] + wm1[(128 + k) * 128 + j]);
        #pragma unroll
        for (int t = lane; t < 64; t += 32)
            acc += be2l[t] * wm1[(256 + t) * 128 + j];
        #pragma unroll
        for (int o = 16; o; o >>= 1) acc += __shfl_xor_sync(0xffffffffu, acc, o);
        if (lane == 0) {
            float half = 0.5f * (bm1[l * 128 + j] + acc);
            bch[l * 256 + j] = half;
            bch[l * 256 + 128 + j] = half;
        }
    }
}

// ================= fused fp16 transpose prep kernel =================
__device__ __forceinline__ void splitw(float w, __half* hi, __half* lo, int o) {
    __half h = __float2half_rn(w);
    hi[o] = h;
    lo[o] = __float2half_rn(w - __half2float(h));
}

// blocks: [0,96) we1t | [96,288) WcT | [288,480) Wm2T | [480,864) W1 | [864,1632) WAB | [1632,1664) Wf
__global__ __launch_bounds__(256) void prep_all(
    const float* __restrict__ We1, const float* __restrict__ WcG,
    const float* __restrict__ Wm2, const float* __restrict__ Wn1,
    const float* __restrict__ WabG, const float* __restrict__ Wf,
    __half* __restrict__ wb, __half* __restrict__ nbw,
    __half* __restrict__ wfb)
{
    int b = blockIdx.x, tid = threadIdx.x;
    if (b < 96) {
        int l = b / 32;
        int idx = (b % 32) * 256 + tid;
        int n = idx >> 6, k = idx & 63;
        float w = We1[(size_t)l * 8192 + k * 128 + n];
        __half* base = wb + (size_t)l * WP_LAYER_ELEMS;
        base[WO_WE1H + n * 72 + k] = __float2half_rn(w);
    } else if (b < 288) {
        int lb = b - 96;
        int l = lb / 64;
        int idx = (lb % 64) * 256 + tid;
        int n = idx >> 7, k = idx & 127;
        float w = WcG[(size_t)l * 16384 + k * 128 + n];
        __half* base = wb + (size_t)l * WP_LAYER_ELEMS;
        base[WO_WCH + n * 136 + k] = __float2half_rn(w);
    } else if (b < 480) {
        int lb = b - 288;
        int l = lb / 64;
        int idx = (lb % 64) * 256 + tid;
        int n = idx >> 7, k = idx & 127;
        float w = Wm2[(size_t)l * 16384 + k * 128 + n];
        __half* base = wb + (size_t)l * WP_LAYER_ELEMS;
        base[WO_WM2H + n * 136 + k] = __float2half_rn(w);
    } else if (b < 864) {
        int lb = b - 480;
        int l = lb / 128;
        int idx = (lb % 128) * 256 + tid;
        int n = idx & 255, k = idx >> 8;
        float w = Wn1[(size_t)l * 32768 + idx];
        __half* base = nbw + (size_t)l * NP_LAYER_ELEMS + NP_W1;
        splitw(w, base, base + 256 * 136, n * 136 + k);
    } else if (b < 1632) {
        int lb = b - 864;
        int l = lb / 256;
        int idx = (lb % 256) * 256 + tid;
        int n = idx & 255, k = idx >> 8;
        float w = WabG[(size_t)l * 65536 + idx];
        __half* base = nbw + (size_t)l * NP_LAYER_ELEMS + NP_WAB;
        splitw(w, base, base + 256 * 264, n * 264 + k);
    } else {
        int idx = (b - 1632) * 256 + tid;
        int n = idx & 63, k = idx >> 6;
        splitw(Wf[idx], wfb, wfb + 64 * 136, n * 136 + k);
    }
}

// ================= counting sort of edges by dst =================
__global__ void zero_init(int* __restrict__ hist, int* __restrict__ cursor,
                          float* __restrict__ agg, int N) {
    int i = blockIdx.x * blockDim.x + threadIdx.x;
    if (i < N) { hist[i] = 0; cursor[i] = 0; }
    if (i < N * 32) ((float4*)agg)[i] = make_float4(0.f, 0.f, 0.f, 0.f);
}

__global__ void hist_kernel(const int* __restrict__ dst, int* __restrict__ hist, int E) {
    int e = blockIdx.x * blockDim.x + threadIdx.x;
    if (e < E) atomicAdd(&hist[dst[e]], 1);
}

__global__ void scan1(const int* __restrict__ hist, int* __restrict__ rowptr,
                      int* __restrict__ bsum, int N) {
    __shared__ int s[256];
    int t = threadIdx.x, i = blockIdx.x * 256 + t;
    int v = (i < N) ? hist[i] : 0;
    s[t] = v;
    __syncthreads();
    #pragma unroll
    for (int o = 1; o < 256; o <<= 1) {
        int u = (t >= o) ? s[t - o] : 0;
        __syncthreads();
        s[t] += u;
        __syncthreads();
    }
    if (i < N) rowptr[i] = s[t];
    if (t == 255) bsum[blockIdx.x] = s[255];
}

__global__ void scan2(int* __restrict__ bsum, int nb) {
    __shared__ int s[256];
    int t = threadIdx.x;
    int orig = (t < nb) ? bsum[t] : 0;
    s[t] = orig;
    __syncthreads();
    #pragma unroll
    for (int o = 1; o < 256; o <<= 1) {
        int u = (t >= o) ? s[t - o] : 0;
        __syncthreads();
        s[t] += u;
        __syncthreads();
    }
    if (t < nb) bsum[t] = s[t] - orig;
}

__global__ void scan3(int* __restrict__ rowptr, const int* __restrict__ hist,
                      const int* __restrict__ bsum, int N, int E) {
    int i = blockIdx.x * blockDim.x + threadIdx.x;
    if (i < N) rowptr[i] = rowptr[i] - hist[i] + bsum[i >> 8];
    if (i == N) rowptr[N] = E;
}

__global__ void scatter_kernel(const int* __restrict__ dst, const int* __restrict__ rowptr,
                               int* __restrict__ cursor, int* __restrict__ perm, int E) {
    int e = blockIdx.x * blockDim.x + threadIdx.x;
    if (e < E) {
        int d = dst[e];
        int pos = rowptr[d] + atomicAdd(&cursor[d], 1);
        perm[pos] = e;
    }
}

// ========== tensor-core node GEMM (fp16 2-term, PERSISTENT over row-blocks) ==========
template<int KCH, int NB, bool RELU>
__global__ __launch_bounds__(256) void ngemm(
    const float* __restrict__ A, const uint4* __restrict__ Wt,
    const float* __restrict__ bias, float* __restrict__ C, int M, int Nfull)
{
    constexpr int K = KCH * 16;
    constexpr int KP = K + 8;
    constexpr int NT = NB * 8;
    extern __shared__ char nsm[];
    __half* Whs = (__half*)nsm;
    __half* Wls = Whs + NT * KP;
    float* bs = (float*)(Wls + NT * KP);

    int tid = threadIdx.x;
    int n0 = blockIdx.y * NT;
    {
        const uint4* hsrc = Wt + n0 * KP / 8;
        const uint4* lsrc = Wt + (Nfull * KP) / 8 + n0 * KP / 8;
        uint4* hdst = (uint4*)Whs;
        uint4* ldst = (uint4*)Wls;
        constexpr int CNT = NT * KP / 8;
        for (int i = tid; i < CNT; i += 256) { hdst[i] = hsrc[i]; ldst[i] = lsrc[i]; }
        if (tid < NT) bs[tid] = bias ? bias[n0 + tid] : 0.f;
    }
    __syncthreads();

    int lane = tid & 31, wid = tid >> 5;
    int qr = lane >> 2, qc = (lane & 3) * 2;

    int nMB = (M + 127) >> 7;
    for (int mb = blockIdx.x; mb < nMB; mb += gridDim.x) {
        int m0 = (mb * 8 + wid) * 16;
        int r0 = m0 + qr, r1 = r0 + 8;
        bool v0 = r0 < M, v1 = r1 < M;
        const float* a0 = A + (size_t)(v0 ? r0 : 0) * K;
        const float* a1 = A + (size_t)(v1 ? r1 : 0) * K;

        float acc[NB][4];
        #pragma unroll
        for (int nb = 0; nb < NB; nb++) {
            acc[nb][0] = acc[nb][1] = acc[nb][2] = acc[nb][3] = 0.f;
        }

        #pragma unroll 2
        for (int j = 0; j < KCH; j++) {
            uint32_t Ah[4];
            float2 x0 = *(const float2*)(a0 + 16 * j + qc);
            float2 x1 = *(const float2*)(a1 + 16 * j + qc);
            float2 x2 = *(const float2*)(a0 + 16 * j + qc + 8);
            float2 x3 = *(const float2*)(a1 + 16 * j + qc + 8);
            Ah[0] = packh(x0.x, x0.y);
            Ah[1] = packh(x1.x, x1.y);
            Ah[2] = packh(x2.x, x2.y);
            Ah[3] = packh(x3.x, x3.y);
            #pragma unroll
            for (int nb = 0; nb < NB; nb++) {
                const __half* ph = Whs + (8 * nb + qr) * KP + 16 * j + qc;
                const __half* pl = Wls + (8 * nb + qr) * KP + 16 * j + qc;
                uint32_t bh0 = *(const uint32_t*)ph;
                uint32_t bh1 = *(const uint32_t*)(ph + 8);
                uint32_t bl0 = *(const uint32_t*)pl;
                uint32_t bl1 = *(const uint32_t*)(pl + 8);
                mma_f16(acc[nb], Ah, bh0, bh1);
                mma_f16(acc[nb], Ah, bl0, bl1);
            }
        }

        #pragma unroll
        for (int nb = 0; nb < NB; nb++) {
            int col = 8 * nb + qc;
            float b0v = bs[col], b1v = bs[col + 1];
            float u0 = acc[nb][0] + b0v, u1 = acc[nb][1] + b1v;
            float u2 = acc[nb][2] + b0v, u3 = acc[nb][3] + b1v;
            if (RELU) {
                u0 = fmaxf(u0, 0.f); u1 = fmaxf(u1, 0.f);
                u2 = fmaxf(u2, 0.f); u3 = fmaxf(u3, 0.f);
            }
            if (v0) *(float2*)(C + (size_t)r0 * Nfull + n0 + col) = make_float2(u0, u1);
            if (v1) *(float2*)(C + (size_t)r1 * Nfull + n0 + col) = make_float2(u2, u3);
        }
    }
}

// ===== mma.sync fused edge kernel (fp16 1-term weights, M=16, 384 threads) =====
#define EDGE3_SMEM (88064 + 512)
#define EDGE_THREADS 384
#define EDGE_WARPS 12

template<int NC>
__device__ __forceinline__ void stage_mma(
    float acc[16][4], const uint32_t Ah[8][4],
    const __half* __restrict__ Wh,
    int KP, int qr, int qc)
{
    #pragma unroll
    for (int j = 0; j < NC; j++) {
        #pragma unroll
        for (int nb = 0; nb < 16; nb++) {
            const __half* ph = Wh + (8 * nb + qr) * KP + 16 * j + qc;
            uint32_t bh0 = *(const uint32_t*)ph;
            uint32_t bh1 = *(const uint32_t*)(ph + 8);
            mma_f16(acc[nb], Ah[j], bh0, bh1);
        }
    }
}

__global__ __launch_bounds__(EDGE_THREADS, 1) void edge_kernel9(
    const float* __restrict__ ea,
    const int* __restrict__ src, const int* __restrict__ dst,
    const int* __restrict__ perm,
    const uint4* __restrict__ wpack,
    const float* __restrict__ be1,
    const float* __restrict__ ab, float* __restrict__ agg, int E)
{
    extern __shared__ char smem[];
    __half* W = (__half*)smem;
    float* be1s = (float*)(smem + 88064);

    int tid = threadIdx.x;
    {
        uint4* s4 = (uint4*)smem;
        for (int i = tid; i < 5504; i += EDGE_THREADS) s4[i] = wpack[i];
        if (tid < 128) be1s[tid] = be1[tid];
    }
    __syncthreads();

    const __half* We1h = W + WO_WE1H;
    const __half* Wch  = W + WO_WCH;
    const __half* Wm2h = W + WO_WM2H;

    int lane = tid & 31, wid = tid >> 5;
    int qr = lane >> 2;
    int qc = (lane & 3) * 2;

    int nG = (E + 15) >> 4;
    for (int g = blockIdx.x * EDGE_WARPS + wid; g < nG; g += gridDim.x * EDGE_WARPS) {
        int p0 = g << 4;
        int pr0 = p0 + qr, pr1 = pr0 + 8;
        bool v0 = pr0 < E, v1 = pr1 < E;
        int ec0 = v0 ? perm[pr0] : 0, ec1 = v1 ? perm[pr1] : 0;
        int d0 = dst[ec0], d1 = dst[ec1];
        int s0 = src[ec0], s1 = src[ec1];

        uint32_t Ah[8][4];
        float acc[16][4];

        #pragma unroll
        for (int j = 0; j < 4; j++) {
            const float* r0p = ea + (size_t)ec0 * 64 + 16 * j + qc;
            const float* r1p = ea + (size_t)ec1 * 64 + 16 * j + qc;
            float2 x0 = *(const float2*)r0p;
            float2 x1 = *(const float2*)r1p;
            float2 x2 = *(const float2*)(r0p + 8);
            float2 x3 = *(const float2*)(r1p + 8);
            Ah[j][0] = packh(x0.x, x0.y);
            Ah[j][1] = packh(x1.x, x1.y);
            Ah[j][2] = packh(x2.x, x2.y);
            Ah[j][3] = packh(x3.x, x3.y);
        }

        // S1
        #pragma unroll
        for (int nb = 0; nb < 16; nb++)
            #pragma unroll
            for (int q = 0; q < 4; q++) acc[nb][q] = 0.f;
        stage_mma<4>(acc, Ah, We1h, 72, qr, qc);
        #pragma unroll
        for (int nb = 0; nb < 16; nb++) {
            int col = 8 * nb + qc;
            float b0 = be1s[col], b1 = be1s[col + 1];
            float u0 = fmaxf(acc[nb][0] + b0, 0.f);
            float u1 = fmaxf(acc[nb][1] + b1, 0.f);
            float u2 = fmaxf(acc[nb][2] + b0, 0.f);
            float u3 = fmaxf(acc[nb][3] + b1, 0.f);
            int j = nb >> 1, q = (nb & 1) * 2;
            Ah[j][q]     = packh(u0, u1);
            Ah[j][q + 1] = packh(u2, u3);
        }

        // S2  (bc folded into ab via bch bias in the WAB gemm)
        #pragma unroll
        for (int nb = 0; nb < 16; nb++)
            #pragma unroll
            for (int q = 0; q < 4; q++) acc[nb][q] = 0.f;
        stage_mma<8>(acc, Ah, Wch, 136, qr, qc);
        {
            const float* a0p = ab + (size_t)d0 * 256;
            const float* a1p = ab + (size_t)d1 * 256;
            const float* b0p = ab + (size_t)s0 * 256 + 128;
            const float* b1p = ab + (size_t)s1 * 256 + 128;
            #pragma unroll
            for (int nb = 0; nb < 16; nb++) {
                int col = 8 * nb + qc;
                float2 ga0 = *(const float2*)(a0p + col);
                float2 ga1 = *(const float2*)(a1p + col);
                float2 gb0 = *(const float2*)(b0p + col);
                float2 gb1 = *(const float2*)(b1p + col);
                float u0 = fmaxf(acc[nb][0] + ga0.x + gb0.x, 0.f);
                float u1 = fmaxf(acc[nb][1] + ga0.y + gb0.y, 0.f);
                float u2 = fmaxf(acc[nb][2] + ga1.x + gb1.x, 0.f);
                float u3 = fmaxf(acc[nb][3] + ga1.y + gb1.y, 0.f);
                int j = nb >> 1, q = (nb & 1) * 2;
                Ah[j][q]     = packh(u0, u1);
                Ah[j][q + 1] = packh(u2, u3);
            }
        }

        // S3 + deduped atomic scatter (sorted dst => rows qr and qr+8 often share dst)
        #pragma unroll
        for (int nb = 0; nb < 16; nb++)
            #pragma unroll
            for (int q = 0; q < 4; q++) acc[nb][q] = 0.f;
        stage_mma<8>(acc, Ah, Wm2h, 136, qr, qc);
        {
            float* g0 = agg + (size_t)d0 * 128;
            float* g1 = agg + (size_t)d1 * 128;
            bool same = v1 && (d0 == d1);
            #pragma unroll
            for (int nb = 0; nb < 16; nb++) {
                int col = 8 * nb + qc;
                if (same) {
                    asm volatile("red.global.add.v2.f32 [%0], {%1, %2};"
                                 :: "l"(g0 + col),
                                    "f"(acc[nb][0] + acc[nb][2]),
                                    "f"(acc[nb][1] + acc[nb][3]) : "memory");
                } else {
                    if (v0)
                        asm volatile("red.global.add.v2.f32 [%0], {%1, %2};"
                                     :: "l"(g0 + col), "f"(acc[nb][0]), "f"(acc[nb][1]) : "memory");
                    if (v1)
                        asm volatile("red.global.add.v2.f32 [%0], {%1, %2};"
                                     :: "l"(g1 + col), "f"(acc[nb][2]), "f"(acc[nb][3]) : "memory");
                }
            }
        }
    }
}

// ================= LayerNorm + relu (+ agg re-zero) =================
__global__ void ln_kernel(float* __restrict__ agg, const int* __restrict__ rowptr,
                          const float* __restrict__ bm2, const float* __restrict__ lnw,
                          const float* __restrict__ lnb, float* __restrict__ xout, int N)
{
    int node = (blockIdx.x * blockDim.x + threadIdx.x) >> 5;
    int lane = threadIdx.x & 31;
    if (node >= N) return;
    float d = (float)(rowptr[node + 1] - rowptr[node]);
    float inv = 1.f / fmaxf(d, 1.f);
    float add = (d > 0.f) ? 1.f : 0.f;
    float4 v = ((const float4*)agg)[(size_t)node * 32 + lane];
    ((float4*)agg)[(size_t)node * 32 + lane] = make_float4(0.f, 0.f, 0.f, 0.f);
    float4 b = ((const float4*)bm2)[lane];
    v.x = v.x * inv + add * b.x;
    v.y = v.y * inv + add * b.y;
    v.z = v.z * inv + add * b.z;
    v.w = v.w * inv + add * b.w;
    float s = v.x + v.y + v.z + v.w;
    #pragma unroll
    for (int o = 16; o; o >>= 1) s += __shfl_xor_sync(0xffffffffu, s, o);
    float mu = s * (1.f / 128.f);
    float d0 = v.x - mu, d1 = v.y - mu, d2 = v.z - mu, d3 = v.w - mu;
    float q = d0 * d0 + d1 * d1 + d2 * d2 + d3 * d3;
    #pragma unroll
    for (int o = 16; o; o >>= 1) q += __shfl_xor_sync(0xffffffffu, q, o);
    float rs = rsqrtf(q * (1.f / 128.f) + 1e-5f);
    float4 w = ((const float4*)lnw)[lane];
    float4 bb = ((const float4*)lnb)[lane];
    float4 o;
    o.x = fmaxf(d0 * rs * w.x + bb.x, 0.f);
    o.y = fmaxf(d1 * rs * w.y + bb.y, 0.f);
    o.z = fmaxf(d2 * rs * w.z + bb.z, 0.f);
    o.w = fmaxf(d3 * rs * w.w + bb.w, 0.f);
    ((float4*)xout)[(size_t)node * 32 + lane] = o;
}

// ================= host =================
extern "C" void kernel_launch(void* const* d_in, const int* in_sizes, int n_in,
                              void* d_out, int out_size)
{
    const float* x    = (const float*)d_in[0];
    const float* ea   = (const float*)d_in[1];
    const int*   eidx = (const int*)  d_in[2];
    const float* Wn1  = (const float*)d_in[3];
    const float* bn1  = (const float*)d_in[4];
    const float* Wn2  = (const float*)d_in[5];
    const float* bn2  = (const float*)d_in[6];
    const float* We1  = (const float*)d_in[7];
    const float* be1  = (const float*)d_in[8];
    const float* We2  = (const float*)d_in[9];
    const float* be2  = (const float*)d_in[10];
    const float* Wm1  = (const float*)d_in[11];
    const float* bm1  = (const float*)d_in[12];
    const float* Wm2  = (const float*)d_in[13];
    const float* bm2  = (const float*)d_in[14];
    const float* lnw  = (const float*)d_in[15];
    const float* lnb  = (const float*)d_in[16];
    const float* Wf   = (const float*)d_in[17];
    const float* bf   = (const float*)d_in[18];

    int N = in_sizes[0] / 128;
    int E = in_sizes[1] / 64;
    const int* srcp = eidx;
    const int* dstp = eidx + E;

    float *h1n, *ab, *xb, *agg, *Wab, *Wc, *bch;
    int *hist, *cursor, *rowptr, *bsum, *perm;
    uint4 *wpack, *wnode, *wf;
    cudaGetSymbolAddress((void**)&h1n, g_h1n);
    cudaGetSymbolAddress((void**)&ab,  g_ab);
    cudaGetSymbolAddress((void**)&xb,  g_x);
    cudaGetSymbolAddress((void**)&agg, g_agg);
    cudaGetSymbolAddress((void**)&Wab, g_Wab);
    cudaGetSymbolAddress((void**)&Wc,  g_Wc);
    cudaGetSymbolAddress((void**)&bch, g_bch);
    cudaGetSymbolAddress((void**)&hist, g_hist);
    cudaGetSymbolAddress((void**)&cursor, g_cursor);
    cudaGetSymbolAddress((void**)&rowptr, g_rowptr);
    cudaGetSymbolAddress((void**)&bsum, g_bsum);
    cudaGetSymbolAddress((void**)&perm, g_perm);
    cudaGetSymbolAddress((void**)&wpack, g_wpack);
    cudaGetSymbolAddress((void**)&wnode, g_wnode);
    cudaGetSymbolAddress((void**)&wf, g_wf);
    __half* wb = (__half*)wpack;
    __half* nbw = (__half*)wnode;
    __half* wfb = (__half*)wf;

    cudaFuncSetAttribute(edge_kernel9, cudaFuncAttributeMaxDynamicSharedMemorySize,
                         EDGE3_SMEM);
    int smW1  = 2 * 128 * 136 * 2 + 512;   // ngemm<8,16>
    int smWab = 2 * 128 * 264 * 2 + 512;   // ngemm<16,16>
    int smWf  = 2 * 64 * 136 * 2 + 256;    // ngemm<8,8>
    cudaFuncSetAttribute(ngemm<8, 16, true>,   cudaFuncAttributeMaxDynamicSharedMemorySize, smW1);
    cudaFuncSetAttribute(ngemm<16, 16, false>, cudaFuncAttributeMaxDynamicSharedMemorySize, smWab);
    cudaFuncSetAttribute(ngemm<8, 8, false>,   cudaFuncAttributeMaxDynamicSharedMemorySize, smWf);

    int nBlk = (N + 255) / 256;
    zero_init<<<(N * 32 + 255) / 256, 256>>>(hist, cursor, agg, N);
    hist_kernel<<<(E + 255) / 256, 256>>>(dstp, hist, E);
    scan1<<<nBlk, 256>>>(hist, rowptr, bsum, N);
    scan2<<<1, 256>>>(bsum, nBlk);
    scan3<<<(N + 256) / 256, 256>>>(rowptr, hist, bsum, N, E);
    scatter_kernel<<<(E + 255) / 256, 256>>>(dstp, rowptr, cursor, perm, E);
    fuse_all<<<1008, 256>>>(Wn2, Wm1, We2, bn2, be2, bm1, Wab, Wc, bch);
    prep_all<<<1664, 256>>>(We1, Wc, Wm2, Wn1, Wab, Wf, wb, nbw, wfb);

    const float* curx = x;
    for (int l = 0; l < LLAYERS; l++) {
        __half* npb = nbw + (size_t)l * NP_LAYER_ELEMS;
        ngemm<8, 16, true><<<dim3(74, 2), 256, smW1>>>(
            curx, (const uint4*)(npb + NP_W1), bn1 + l * 256, h1n, N, 256);
        ngemm<16, 16, false><<<dim3(74, 2), 256, smWab>>>(
            h1n, (const uint4*)(npb + NP_WAB), bch + l * 256, ab, N, 256);
        edge_kernel9<<<148, EDGE_THREADS, EDGE3_SMEM>>>(
            ea, srcp, dstp, perm,
            (const uint4*)(wb + (size_t)l * WP_LAYER_ELEMS),
            be1 + l * 128, ab, agg, E);
        ln_kernel<<<(N + 7) / 8, 256>>>(agg, rowptr, bm2 + l * 128, lnw + l * 128,
                                        lnb + l * 128, xb, N);
        curx = xb;
    }
    ngemm<8, 8, false><<<dim3(148, 1), 256, smWf>>>(
        curx, (const uint4*)wfb, bf, (float*)d_out, N, 64);
}